// round 14
// baseline (speedup 1.0000x reference)
#include <cuda_runtime.h>
#include <cuda_fp16.h>
#include <stdint.h>
#include <math.h>

#define Bsz   2
#define Slen  2048
#define Hdim  1024
#define NHn   16
#define HDn   64
#define Mtot  (Bsz*Slen)
#define EPSf  1e-12f
#define WSCL  256.f
#define WDSC  (1.f/256.f)

// -------- scratch (no allocations allowed) --------
__device__ float g_y[Mtot*Hdim];
__device__ __half g_xh[Mtot*Hdim];
__device__ __half g_wh[4*Hdim*Hdim];
__device__ __half g_qh[Mtot*Hdim];
__device__ __half g_kh[Mtot*Hdim];
__device__ __half g_vh[Mtot*Hdim];
__device__ __half g_ch[Mtot*Hdim];

// ---------------- helpers ----------------
__device__ __forceinline__ uint32_t smem_u32(const void* p) {
    uint32_t a;
    asm("{ .reg .u64 t; cvta.to.shared.u64 t, %1; cvt.u32.u64 %0, t; }" : "=r"(a) : "l"(p));
    return a;
}
__device__ __forceinline__ void cp16(uint32_t dst, const void* src) {
    asm volatile("cp.async.cg.shared.global [%0], [%1], 16;" :: "r"(dst), "l"(src));
}
#define CP_COMMIT() asm volatile("cp.async.commit_group;")
#define CP_WAIT(n)  asm volatile("cp.async.wait_group %0;" :: "n"(n))
#define LDSM_X4(r0,r1,r2,r3,addr) \
    asm volatile("ldmatrix.sync.aligned.m8n8.x4.shared.b16 {%0,%1,%2,%3}, [%4];" \
        : "=r"(r0),"=r"(r1),"=r"(r2),"=r"(r3) : "r"(addr))
#define LDSM_X4_T(r0,r1,r2,r3,addr) \
    asm volatile("ldmatrix.sync.aligned.m8n8.x4.trans.shared.b16 {%0,%1,%2,%3}, [%4];" \
        : "=r"(r0),"=r"(r1),"=r"(r2),"=r"(r3) : "r"(addr))
#define MMAH(c, a, b) \
    asm volatile("mma.sync.aligned.m16n8k16.row.col.f32.f16.f16.f32 " \
        "{%0,%1,%2,%3}, {%4,%5,%6,%7}, {%8,%9}, {%0,%1,%2,%3};" \
        : "+f"((c)[0]),"+f"((c)[1]),"+f"((c)[2]),"+f"((c)[3]) \
        : "r"((a)[0]),"r"((a)[1]),"r"((a)[2]),"r"((a)[3]), "r"((b)[0]),"r"((b)[1]))

__device__ __forceinline__ uint32_t pk_h2(float a, float b) {
    __half2 h = __floats2half2_rn(a, b);
    return *(uint32_t*)&h;
}

// ---------------- fused prep ----------------
__global__ void prep_kernel(const float* __restrict__ x,
                            const float* __restrict__ Wq, const float* __restrict__ Wk,
                            const float* __restrict__ Wv, const float* __restrict__ Wo,
                            __half* __restrict__ xh, __half* __restrict__ wh)
{
    const int bid = blockIdx.x, tid = threadIdx.x;
    if (bid < 4096) {
        const int i = bid * 256 + tid;
        float4 v = ((const float4*)x)[i];
        __half2 a = __floats2half2_rn(v.x, v.y);
        __half2 b = __floats2half2_rn(v.z, v.w);
        ((uint2*)xh)[i] = make_uint2(*(uint32_t*)&a, *(uint32_t*)&b);
    } else {
        const int wb = bid - 4096;
        const int w = wb >> 10;
        const float* src = (w == 0) ? Wq : (w == 1) ? Wk : (w == 2) ? Wv : Wo;
        const int i = (wb & 1023) * 256 + tid;
        float4 v = ((const float4*)src)[i];
        __half2 a = __floats2half2_rn(v.x * WSCL, v.y * WSCL);
        __half2 b = __floats2half2_rn(v.z * WSCL, v.w * WSCL);
        ((uint2*)(wh + (size_t)w * Hdim * Hdim))[i] = make_uint2(*(uint32_t*)&a, *(uint32_t*)&b);
    }
}

// ---------------- fp16 GEMM core: 3-stage ring, BK=64, XOR-swizzled 128B rows ----------------
// Tensor/stage: 128 rows x 128B = 16384B. Stage (A+W) = 32768B. 3 stages = 98304B.
#define GT 16384
#define GS 32768

__device__ __forceinline__ void gemm_core_h(
    uint32_t sbase,
    const __half* __restrict__ Ah, const __half* __restrict__ Wh,
    int m0, int n0, float acc[4][4][4])
{
    const int tid = threadIdx.x, wid = tid >> 5, lane = tid & 31;
    const int wm0 = (wid & 1) * 64, wn0 = (wid >> 1) * 32;
    const int a_row = wm0 + (lane & 15);
    const int b_row = wn0 + (lane & 7) + ((lane >> 4) << 3);
    const int cA = (lane >> 4) & 1;          // chunk sub-index for A frag
    const int cB = (lane >> 3) & 1;          // chunk sub-index for B frag
    const int lrr = tid >> 3;                // 0..31 (load row)
    const int lcc = tid & 7;                 // 0..7  (load chunk)

#define GH_LOAD(st, k0) do { \
        const uint32_t sb_ = sbase + (st) * GS; \
        _Pragma("unroll") \
        for (int i_ = 0; i_ < 4; i_++) { \
            const int r_ = i_ * 32 + lrr; \
            const int cs_ = lcc ^ ((r_ & 3) << 1); \
            const uint32_t off_ = (uint32_t)(r_ * 128 + cs_ * 16); \
            cp16(sb_ + off_,      Ah + (size_t)(m0 + r_) * Hdim + (k0) + lcc * 8); \
            cp16(sb_ + GT + off_, Wh + (size_t)(n0 + r_) * Hdim + (k0) + lcc * 8); \
        } } while (0)

    GH_LOAD(0, 0);
    CP_COMMIT();
    GH_LOAD(1, 64);
    CP_COMMIT();

    for (int it = 0; it < 16; it++) {
        if (it < 15) { CP_WAIT(1); } else { CP_WAIT(0); }
        __syncthreads();
        if (it + 2 < 16) {
            GH_LOAD((it + 2) % 3, (it + 2) * 64);
            CP_COMMIT();
        }

        const uint32_t sb = sbase + (it % 3) * GS;
        const uint32_t aA = sb, aW = sb + GT;

#pragma unroll
        for (int kf = 0; kf < 4; kf++) {
            uint32_t ah[4][4];
#pragma unroll
            for (int mf = 0; mf < 4; mf++) {
                const int row = a_row + mf * 16;
                const int cs = (2 * kf + cA) ^ ((row & 3) << 1);
                LDSM_X4(ah[mf][0], ah[mf][1], ah[mf][2], ah[mf][3],
                        aA + (uint32_t)(row * 128 + cs * 16));
            }
#pragma unroll
            for (int nfp = 0; nfp < 2; nfp++) {
                const int row = b_row + nfp * 16;
                const int cs = (2 * kf + cB) ^ ((row & 3) << 1);
                uint32_t wh[4];
                LDSM_X4(wh[0], wh[1], wh[2], wh[3],
                        aW + (uint32_t)(row * 128 + cs * 16));
#pragma unroll
                for (int mf = 0; mf < 4; mf++) {
#pragma unroll
                    for (int hf = 0; hf < 2; hf++)
                        MMAH(acc[mf][nfp * 2 + hf], ah[mf], wh + hf * 2);
                }
            }
        }
    }
#undef GH_LOAD
}

// ---- fused QKV projection ----
__global__ void __launch_bounds__(256) gemm_qkv(
    const __half* __restrict__ Ah, const __half* __restrict__ Wh,
    const float* __restrict__ bq, const float* __restrict__ bk, const float* __restrict__ bv,
    __half* __restrict__ qh, __half* __restrict__ kh, __half* __restrict__ vh)
{
    extern __shared__ char dsm[];
    const uint32_t sbase = smem_u32(dsm);
    const int tid = threadIdx.x, wid = tid >> 5, lane = tid & 31;
    const int n0 = blockIdx.x * 128, m0 = blockIdx.y * 128;

    float acc[4][4][4];
#pragma unroll
    for (int i = 0; i < 4; i++)
#pragma unroll
        for (int j = 0; j < 4; j++)
#pragma unroll
            for (int v = 0; v < 4; v++) acc[i][j][v] = 0.f;

    gemm_core_h(sbase, Ah, Wh, m0, n0, acc);

    const int proj = n0 >> 10;
    const float* bias = (proj == 0) ? bq : (proj == 1) ? bk : bv;
    __half* outH = (proj == 0) ? qh : (proj == 1) ? kh : vh;

    const int wm0 = (wid & 1) * 64, wn0 = (wid >> 1) * 32;
    const int rbase = m0 + wm0 + (lane >> 2);
    const int cbase = n0 + wn0 + (lane & 3) * 2;
#pragma unroll
    for (int mf = 0; mf < 4; mf++) {
#pragma unroll
        for (int nf = 0; nf < 4; nf++) {
#pragma unroll
            for (int half = 0; half < 2; half++) {
                const int r = rbase + mf * 16 + half * 8;
                const int c = cbase + nf * 8;
                const int np = c & 1023;
                float v0 = fmaf(acc[mf][nf][half*2+0], WDSC, bias[np]);
                float v1 = fmaf(acc[mf][nf][half*2+1], WDSC, bias[np+1]);
                const int b = r >> 11, s = r & (Slen - 1);
                const int h = np >> 6, d = np & 63;
                const size_t idx = (((size_t)(b * NHn + h) * Slen) + s) * HDn + d;
                *(uint32_t*)(outH + idx) = pk_h2(v0, v1);
            }
        }
    }
}

// ---- output projection ----
__global__ void __launch_bounds__(256) gemm_out(
    const __half* __restrict__ Ah, const __half* __restrict__ Wh,
    const float* __restrict__ bias, const float* __restrict__ res, float* __restrict__ out)
{
    extern __shared__ char dsm[];
    const uint32_t sbase = smem_u32(dsm);
    const int tid = threadIdx.x, wid = tid >> 5, lane = tid & 31;
    const int n0 = blockIdx.x * 128, m0 = blockIdx.y * 128;

    float acc[4][4][4];
#pragma unroll
    for (int i = 0; i < 4; i++)
#pragma unroll
        for (int j = 0; j < 4; j++)
#pragma unroll
            for (int v = 0; v < 4; v++) acc[i][j][v] = 0.f;

    gemm_core_h(sbase, Ah, Wh, m0, n0, acc);

    const int wm0 = (wid & 1) * 64, wn0 = (wid >> 1) * 32;
    const int rbase = m0 + wm0 + (lane >> 2);
    const int cbase = n0 + wn0 + (lane & 3) * 2;
#pragma unroll
    for (int mf = 0; mf < 4; mf++) {
#pragma unroll
        for (int nf = 0; nf < 4; nf++) {
#pragma unroll
            for (int half = 0; half < 2; half++) {
                const int r = rbase + mf * 16 + half * 8;
                const int c = cbase + nf * 8;
                const size_t idx = (size_t)r * Hdim + c;
                float2 rv = *(const float2*)(res + idx);
                float2 o;
                o.x = fmaf(acc[mf][nf][half*2+0], WDSC, bias[c] + rv.x);
                o.y = fmaf(acc[mf][nf][half*2+1], WDSC, bias[c+1] + rv.y);
                *(float2*)(out + idx) = o;
            }
        }
    }
}

// ---------------- fp16 flash attention: 64q/128thr CTA, 3-stage ring, reversed order ----------------
#define ALD 72
#define A_TEN 9216
#define A_STG 18432
#define A_QOFF 55296
__global__ void __launch_bounds__(128) attn_mma(
    const __half* __restrict__ Qh, const __half* __restrict__ Kh,
    const __half* __restrict__ Vh, __half* __restrict__ Ch)
{
    extern __shared__ char dsm[];
    const uint32_t sbase = smem_u32(dsm);
    const int tid = threadIdx.x, wid = tid >> 5, lane = tid & 31;
    const int qt = (int)gridDim.x - 1 - (int)blockIdx.x;
    const int h = blockIdx.y, b = blockIdx.z;
    const int m0 = qt * 64, wq0 = wid * 16;
    const int ktmax = qt;
    const size_t base = (size_t)(b * NHn + h) * Slen * HDn;

    {
        const __half* srcH = Qh + base + (size_t)m0 * HDn;
#pragma unroll
        for (int i = 0; i < 4; i++) {
            int u = i * 128 + tid, r = u >> 3, c = u & 7;
            int cs = c ^ ((r & 3) << 1);
            *(uint4*)(dsm + A_QOFF + (r * ALD + cs * 8) * 2) = *(const uint4*)(srcH + r * 64 + c * 8);
        }
    }
    __syncthreads();

    const int rA = (lane & 7) + ((lane >> 3) & 1) * 8;
    const int cA = (lane >> 4) & 1;
    const int rB = (lane & 7) + ((lane >> 4) << 3);
    const int cB = (lane >> 3) & 1;
    const int swzA = (rA & 3) << 1;
    const int swzB = (rB & 3) << 1;

    uint32_t qfh[4][4];
    {
        const int row = wq0 + rA;
        const uint32_t rb = (uint32_t)(row * (ALD * 2));
        const int swz = (row & 3) << 1;
#pragma unroll
        for (int kb = 0; kb < 4; kb++) {
            const uint32_t off = rb + (uint32_t)(((2 * kb + cA) ^ swz) * 16);
            LDSM_X4(qfh[kb][0], qfh[kb][1], qfh[kb][2], qfh[kb][3], sbase + A_QOFF + off);
        }
    }

#define A_LOAD(st, k0) do { \
        const uint32_t sb_ = sbase + (st) * A_STG; \
        const __half* kp_ = Kh + base + (size_t)(k0) * HDn; \
        const __half* vp_ = Vh + base + (size_t)(k0) * HDn; \
        _Pragma("unroll") \
        for (int i_ = 0; i_ < 4; i_++) { \
            int u_ = i_ * 128 + tid, r_ = u_ >> 3, c_ = u_ & 7; \
            int cs_ = c_ ^ ((r_ & 3) << 1); \
            uint32_t so_ = (uint32_t)((r_ * ALD + cs_ * 8) * 2); \
            int go_ = r_ * 64 + c_ * 8; \
            cp16(sb_ + so_,         kp_ + go_); \
            cp16(sb_ + A_TEN + so_, vp_ + go_); \
        } } while (0)

    A_LOAD(0, 0);
    CP_COMMIT();
    if (ktmax >= 1) { A_LOAD(1, 64); CP_COMMIT(); }

    float o[8][4];
#pragma unroll
    for (int i = 0; i < 8; i++)
#pragma unroll
        for (int v = 0; v < 4; v++) o[i][v] = 0.f;
    float mr0 = -1e30f, mr1 = -1e30f, lr0 = 0.f, lr1 = 0.f;

    for (int kt = 0; kt <= ktmax; kt++) {
        if (kt < ktmax) { CP_WAIT(1); } else { CP_WAIT(0); }
        __syncthreads();
        if (kt + 2 <= ktmax) {
            A_LOAD((kt + 2) % 3, (kt + 2) * 64);
            CP_COMMIT();
        }

        const uint32_t sb = sbase + (kt % 3) * A_STG;
        const uint32_t aKh = sb, aVh = sb + A_TEN;

        float s[8][4];
#pragma unroll
        for (int i = 0; i < 8; i++)
#pragma unroll
            for (int v = 0; v < 4; v++) s[i][v] = 0.f;
#pragma unroll
        for (int kb = 0; kb < 4; kb++) {
#pragma unroll
            for (int np = 0; np < 4; np++) {
                const int row = np * 16 + rB;
                const uint32_t off = (uint32_t)(row * (ALD * 2) + (((2 * kb + cB) ^ swzB)) * 16);
                uint32_t kh[4];
                LDSM_X4(kh[0], kh[1], kh[2], kh[3], aKh + off);
                MMAH(s[2*np],   qfh[kb], kh);
                MMAH(s[2*np+1], qfh[kb], kh + 2);
            }
        }

#pragma unroll
        for (int nf = 0; nf < 8; nf++)
#pragma unroll
            for (int v = 0; v < 4; v++) s[nf][v] *= 0.125f;
        if (kt == qt) {
            const int row0 = wq0 + (lane >> 2), row1 = row0 + 8;
            const int colb = (lane & 3) * 2;
#pragma unroll
            for (int nf = 0; nf < 8; nf++) {
                const int c0 = nf * 8 + colb, c1 = c0 + 1;
                if (c0 > row0) s[nf][0] = -1e30f;
                if (c1 > row0) s[nf][1] = -1e30f;
                if (c0 > row1) s[nf][2] = -1e30f;
                if (c1 > row1) s[nf][3] = -1e30f;
            }
        }

        float mx0 = s[0][0], mx1 = s[0][2];
#pragma unroll
        for (int nf = 0; nf < 8; nf++) {
            mx0 = fmaxf(mx0, fmaxf(s[nf][0], s[nf][1]));
            mx1 = fmaxf(mx1, fmaxf(s[nf][2], s[nf][3]));
        }
        mx0 = fmaxf(mx0, __shfl_xor_sync(0xffffffffu, mx0, 1));
        mx0 = fmaxf(mx0, __shfl_xor_sync(0xffffffffu, mx0, 2));
        mx1 = fmaxf(mx1, __shfl_xor_sync(0xffffffffu, mx1, 1));
        mx1 = fmaxf(mx1, __shfl_xor_sync(0xffffffffu, mx1, 2));
        const float nm0 = fmaxf(mr0, mx0), nm1 = fmaxf(mr1, mx1);
        const float cr0 = __expf(mr0 - nm0), cr1 = __expf(mr1 - nm1);
        lr0 *= cr0; lr1 *= cr1;
#pragma unroll
        for (int nf = 0; nf < 8; nf++) {
            o[nf][0] *= cr0; o[nf][1] *= cr0;
            o[nf][2] *= cr1; o[nf][3] *= cr1;
        }
        mr0 = nm0; mr1 = nm1;

        uint32_t ph[8], phb[8];
#pragma unroll
        for (int nf = 0; nf < 8; nf++) {
            float p0 = __expf(s[nf][0] - nm0), p1 = __expf(s[nf][1] - nm0);
            float p2 = __expf(s[nf][2] - nm1), p3 = __expf(s[nf][3] - nm1);
            lr0 += p0 + p1; lr1 += p2 + p3;
            ph[nf]  = pk_h2(p0, p1);
            phb[nf] = pk_h2(p2, p3);
        }

#pragma unroll
        for (int kb = 0; kb < 4; kb++) {
            uint32_t pah[4] = { ph[2*kb], phb[2*kb], ph[2*kb+1], phb[2*kb+1] };
            const int row = kb * 16 + rA;
            const uint32_t rb = (uint32_t)(row * (ALD * 2));
#pragma unroll
            for (int np = 0; np < 4; np++) {
                const uint32_t off = rb + (uint32_t)(((2 * np + cA) ^ swzA) * 16);
                uint32_t vh[4];
                LDSM_X4_T(vh[0], vh[1], vh[2], vh[3], aVh + off);
                MMAH(o[2*np],   pah, vh);
                MMAH(o[2*np+1], pah, vh + 2);
            }
        }
    }
#undef A_LOAD

    lr0 += __shfl_xor_sync(0xffffffffu, lr0, 1);
    lr0 += __shfl_xor_sync(0xffffffffu, lr0, 2);
    lr1 += __shfl_xor_sync(0xffffffffu, lr1, 1);
    lr1 += __shfl_xor_sync(0xffffffffu, lr1, 2);
    const float iv0 = 1.f / lr0, iv1 = 1.f / lr1;

    const int s0 = m0 + wq0 + (lane >> 2), s1 = s0 + 8;
    const size_t rb0 = (size_t)(b * Slen + s0) * Hdim + h * 64;
    const size_t rb1 = (size_t)(b * Slen + s1) * Hdim + h * 64;
#pragma unroll
    for (int nf = 0; nf < 8; nf++) {
        const int col = nf * 8 + (lane & 3) * 2;
        *(uint32_t*)(Ch + rb0 + col) = pk_h2(o[nf][0] * iv0, o[nf][1] * iv0);
        *(uint32_t*)(Ch + rb1 + col) = pk_h2(o[nf][2] * iv1, o[nf][3] * iv1);
    }
}

// ---------------- LayerNorm ----------------
__global__ void ln_kernel(const float* __restrict__ y, const float* __restrict__ g,
                          const float* __restrict__ be, float* __restrict__ out)
{
    __shared__ float red[256];
    const int row = blockIdx.x, tid = threadIdx.x;
    const float4 v = ((const float4*)(y + (size_t)row * Hdim))[tid];
    float sum = v.x + v.y + v.z + v.w;
    red[tid] = sum; __syncthreads();
    for (int s = 128; s > 0; s >>= 1) { if (tid < s) red[tid] += red[tid + s]; __syncthreads(); }
    const float mu = red[0] * (1.f / 1024.f);
    __syncthreads();
    const float d0 = v.x - mu, d1 = v.y - mu, d2 = v.z - mu, d3 = v.w - mu;
    red[tid] = d0 * d0 + d1 * d1 + d2 * d2 + d3 * d3; __syncthreads();
    for (int s = 128; s > 0; s >>= 1) { if (tid < s) red[tid] += red[tid + s]; __syncthreads(); }
    const float inv = rsqrtf(red[0] * (1.f / 1024.f) + EPSf);
    const float4 gg = ((const float4*)g)[tid];
    const float4 bb = ((const float4*)be)[tid];
    float4 o;
    o.x = d0 * inv * gg.x + bb.x;
    o.y = d1 * inv * gg.y + bb.y;
    o.z = d2 * inv * gg.z + bb.z;
    o.w = d3 * inv * gg.w + bb.w;
    ((float4*)(out + (size_t)row * Hdim))[tid] = o;
}

// ---------------- launch ----------------
extern "C" void kernel_launch(void* const* d_in, const int* in_sizes, int n_in,
                              void* d_out, int out_size)
{
    const float* x    = (const float*)d_in[0];
    const float* Wq   = (const float*)d_in[1];
    const float* bq   = (const float*)d_in[2];
    const float* Wk   = (const float*)d_in[3];
    const float* bk   = (const float*)d_in[4];
    const float* Wv   = (const float*)d_in[5];
    const float* bv   = (const float*)d_in[6];
    const float* Wo   = (const float*)d_in[7];
    const float* bo   = (const float*)d_in[8];
    const float* ln_g = (const float*)d_in[9];
    const float* ln_b = (const float*)d_in[10];
    float* out = (float*)d_out;

    float* yp;
    __half *xh, *wh, *qh, *kh, *vh, *ch;
    cudaGetSymbolAddress((void**)&yp, g_y);
    cudaGetSymbolAddress((void**)&xh, g_xh);
    cudaGetSymbolAddress((void**)&wh, g_wh);
    cudaGetSymbolAddress((void**)&qh, g_qh);
    cudaGetSymbolAddress((void**)&kh, g_kh);
    cudaGetSymbolAddress((void**)&vh, g_vh);
    cudaGetSymbolAddress((void**)&ch, g_ch);

    static bool attr_done = false;
    if (!attr_done) {
        cudaFuncSetAttribute(gemm_qkv, cudaFuncAttributeMaxDynamicSharedMemorySize, 3 * GS);
        cudaFuncSetAttribute(gemm_out, cudaFuncAttributeMaxDynamicSharedMemorySize, 3 * GS);
        cudaFuncSetAttribute(attn_mma, cudaFuncAttributeMaxDynamicSharedMemorySize, A_QOFF + A_TEN);
        attr_done = true;
    }

    const int WSZ = Hdim * Hdim;
    prep_kernel<<<8192, 256>>>(x, Wq, Wk, Wv, Wo, xh, wh);

    gemm_qkv<<<dim3(3 * Hdim / 128, Mtot / 128), 256, 3 * GS>>>(
        xh, wh, bq, bk, bv, qh, kh, vh);

    attn_mma<<<dim3(Slen / 64, NHn, Bsz), 128, A_QOFF + A_TEN>>>(qh, kh, vh, ch);

    gemm_out<<<dim3(Hdim / 128, Mtot / 128), 256, 3 * GS>>>(
        ch, wh + 3 * WSZ, bo, x, yp);

    ln_kernel<<<Mtot, 256>>>(yp, ln_g, ln_b, out);
}

// round 16
// speedup vs baseline: 1.7041x; 1.7041x over previous
#include <cuda_runtime.h>
#include <cuda_fp16.h>
#include <stdint.h>
#include <math.h>

#define Bsz   2
#define Slen  2048
#define Hdim  1024
#define NHn   16
#define HDn   64
#define Mtot  (Bsz*Slen)
#define EPSf  1e-12f
#define WSCL  256.f
#define WDSC  (1.f/256.f)

// -------- scratch (no allocations allowed) --------
__device__ float g_y[Mtot*Hdim];
__device__ __half g_xh[Mtot*Hdim];
__device__ __half g_wh[4*Hdim*Hdim];
__device__ __half g_qh[Mtot*Hdim];
__device__ __half g_kh[Mtot*Hdim];
__device__ __half g_vh[Mtot*Hdim];
__device__ __half g_ch[Mtot*Hdim];

// ---------------- helpers ----------------
__device__ __forceinline__ uint32_t smem_u32(const void* p) {
    uint32_t a;
    asm("{ .reg .u64 t; cvta.to.shared.u64 t, %1; cvt.u32.u64 %0, t; }" : "=r"(a) : "l"(p));
    return a;
}
__device__ __forceinline__ void cp16(uint32_t dst, const void* src) {
    asm volatile("cp.async.cg.shared.global [%0], [%1], 16;" :: "r"(dst), "l"(src));
}
#define CP_COMMIT() asm volatile("cp.async.commit_group;")
#define CP_WAIT(n)  asm volatile("cp.async.wait_group %0;" :: "n"(n))
#define LDSM_X4(r0,r1,r2,r3,addr) \
    asm volatile("ldmatrix.sync.aligned.m8n8.x4.shared.b16 {%0,%1,%2,%3}, [%4];" \
        : "=r"(r0),"=r"(r1),"=r"(r2),"=r"(r3) : "r"(addr))
#define LDSM_X4_T(r0,r1,r2,r3,addr) \
    asm volatile("ldmatrix.sync.aligned.m8n8.x4.trans.shared.b16 {%0,%1,%2,%3}, [%4];" \
        : "=r"(r0),"=r"(r1),"=r"(r2),"=r"(r3) : "r"(addr))
#define MMAH(c, a, b) \
    asm volatile("mma.sync.aligned.m16n8k16.row.col.f32.f16.f16.f32 " \
        "{%0,%1,%2,%3}, {%4,%5,%6,%7}, {%8,%9}, {%0,%1,%2,%3};" \
        : "+f"((c)[0]),"+f"((c)[1]),"+f"((c)[2]),"+f"((c)[3]) \
        : "r"((a)[0]),"r"((a)[1]),"r"((a)[2]),"r"((a)[3]), "r"((b)[0]),"r"((b)[1]))

__device__ __forceinline__ uint32_t pk_h2(float a, float b) {
    __half2 h = __floats2half2_rn(a, b);
    return *(uint32_t*)&h;
}

// ---------------- fused prep ----------------
__global__ void prep_kernel(const float* __restrict__ x,
                            const float* __restrict__ Wq, const float* __restrict__ Wk,
                            const float* __restrict__ Wv, const float* __restrict__ Wo,
                            __half* __restrict__ xh, __half* __restrict__ wh)
{
    const int bid = blockIdx.x, tid = threadIdx.x;
    if (bid < 4096) {
        const int i = bid * 256 + tid;
        float4 v = ((const float4*)x)[i];
        __half2 a = __floats2half2_rn(v.x, v.y);
        __half2 b = __floats2half2_rn(v.z, v.w);
        ((uint2*)xh)[i] = make_uint2(*(uint32_t*)&a, *(uint32_t*)&b);
    } else {
        const int wb = bid - 4096;
        const int w = wb >> 10;
        const float* src = (w == 0) ? Wq : (w == 1) ? Wk : (w == 2) ? Wv : Wo;
        const int i = (wb & 1023) * 256 + tid;
        float4 v = ((const float4*)src)[i];
        __half2 a = __floats2half2_rn(v.x * WSCL, v.y * WSCL);
        __half2 b = __floats2half2_rn(v.z * WSCL, v.w * WSCL);
        ((uint2*)(wh + (size_t)w * Hdim * Hdim))[i] = make_uint2(*(uint32_t*)&a, *(uint32_t*)&b);
    }
}

// ---------------- fp16 GEMM core: 3-stage ring, BK=64, FULL 128B-row swizzle c^(r&7) ----------------
// Tensor/stage: 128 rows x 128B = 16384B. Stage (A+W) = 32768B. 3 stages = 98304B.
#define GT 16384
#define GS 32768

__device__ __forceinline__ void gemm_core_h(
    uint32_t sbase,
    const __half* __restrict__ Ah, const __half* __restrict__ Wh,
    int m0, int n0, float acc[4][4][4])
{
    const int tid = threadIdx.x, wid = tid >> 5, lane = tid & 31;
    const int wm0 = (wid & 1) * 64, wn0 = (wid >> 1) * 32;
    const int a_row = wm0 + (lane & 15);
    const int b_row = wn0 + (lane & 7) + ((lane >> 4) << 3);
    const int cA = (lane >> 4) & 1;          // chunk sub-index for A frag
    const int cB = (lane >> 3) & 1;          // chunk sub-index for B frag
    const int lrr = tid >> 3;                // 0..31 (load row)
    const int lcc = tid & 7;                 // 0..7  (load chunk)

#define GH_LOAD(st, k0) do { \
        const uint32_t sb_ = sbase + (st) * GS; \
        _Pragma("unroll") \
        for (int i_ = 0; i_ < 4; i_++) { \
            const int r_ = i_ * 32 + lrr; \
            const int cs_ = lcc ^ (r_ & 7); \
            const uint32_t off_ = (uint32_t)(r_ * 128 + cs_ * 16); \
            cp16(sb_ + off_,      Ah + (size_t)(m0 + r_) * Hdim + (k0) + lcc * 8); \
            cp16(sb_ + GT + off_, Wh + (size_t)(n0 + r_) * Hdim + (k0) + lcc * 8); \
        } } while (0)

    GH_LOAD(0, 0);
    CP_COMMIT();
    GH_LOAD(1, 64);
    CP_COMMIT();

    for (int it = 0; it < 16; it++) {
        if (it < 15) { CP_WAIT(1); } else { CP_WAIT(0); }
        __syncthreads();
        if (it + 2 < 16) {
            GH_LOAD((it + 2) % 3, (it + 2) * 64);
            CP_COMMIT();
        }

        const uint32_t sb = sbase + (it % 3) * GS;
        const uint32_t aA = sb, aW = sb + GT;

#pragma unroll
        for (int kf = 0; kf < 4; kf++) {
            uint32_t ah[4][4];
#pragma unroll
            for (int mf = 0; mf < 4; mf++) {
                const int row = a_row + mf * 16;
                const int cs = (2 * kf + cA) ^ (row & 7);
                LDSM_X4(ah[mf][0], ah[mf][1], ah[mf][2], ah[mf][3],
                        aA + (uint32_t)(row * 128 + cs * 16));
            }
#pragma unroll
            for (int nfp = 0; nfp < 2; nfp++) {
                const int row = b_row + nfp * 16;
                const int cs = (2 * kf + cB) ^ (row & 7);
                uint32_t wh[4];
                LDSM_X4(wh[0], wh[1], wh[2], wh[3],
                        aW + (uint32_t)(row * 128 + cs * 16));
#pragma unroll
                for (int mf = 0; mf < 4; mf++) {
#pragma unroll
                    for (int hf = 0; hf < 2; hf++)
                        MMAH(acc[mf][nfp * 2 + hf], ah[mf], wh + hf * 2);
                }
            }
        }
    }
#undef GH_LOAD
}

// ---- fused QKV projection ----
__global__ void __launch_bounds__(256, 2) gemm_qkv(
    const __half* __restrict__ Ah, const __half* __restrict__ Wh,
    const float* __restrict__ bq, const float* __restrict__ bk, const float* __restrict__ bv,
    __half* __restrict__ qh, __half* __restrict__ kh, __half* __restrict__ vh)
{
    extern __shared__ char dsm[];
    const uint32_t sbase = smem_u32(dsm);
    const int tid = threadIdx.x, wid = tid >> 5, lane = tid & 31;
    const int n0 = blockIdx.x * 128, m0 = blockIdx.y * 128;

    float acc[4][4][4];
#pragma unroll
    for (int i = 0; i < 4; i++)
#pragma unroll
        for (int j = 0; j < 4; j++)
#pragma unroll
            for (int v = 0; v < 4; v++) acc[i][j][v] = 0.f;

    gemm_core_h(sbase, Ah, Wh, m0, n0, acc);

    const int proj = n0 >> 10;
    const float* bias = (proj == 0) ? bq : (proj == 1) ? bk : bv;
    __half* outH = (proj == 0) ? qh : (proj == 1) ? kh : vh;

    const int wm0 = (wid & 1) * 64, wn0 = (wid >> 1) * 32;
    const int rbase = m0 + wm0 + (lane >> 2);
    const int cbase = n0 + wn0 + (lane & 3) * 2;
#pragma unroll
    for (int mf = 0; mf < 4; mf++) {
#pragma unroll
        for (int nf = 0; nf < 4; nf++) {
#pragma unroll
            for (int half = 0; half < 2; half++) {
                const int r = rbase + mf * 16 + half * 8;
                const int c = cbase + nf * 8;
                const int np = c & 1023;
                float v0 = fmaf(acc[mf][nf][half*2+0], WDSC, bias[np]);
                float v1 = fmaf(acc[mf][nf][half*2+1], WDSC, bias[np+1]);
                const int b = r >> 11, s = r & (Slen - 1);
                const int h = np >> 6, d = np & 63;
                const size_t idx = (((size_t)(b * NHn + h) * Slen) + s) * HDn + d;
                *(uint32_t*)(outH + idx) = pk_h2(v0, v1);
            }
        }
    }
}

// ---- output projection ----
__global__ void __launch_bounds__(256, 2) gemm_out(
    const __half* __restrict__ Ah, const __half* __restrict__ Wh,
    const float* __restrict__ bias, const float* __restrict__ res, float* __restrict__ out)
{
    extern __shared__ char dsm[];
    const uint32_t sbase = smem_u32(dsm);
    const int tid = threadIdx.x, wid = tid >> 5, lane = tid & 31;
    const int n0 = blockIdx.x * 128, m0 = blockIdx.y * 128;

    float acc[4][4][4];
#pragma unroll
    for (int i = 0; i < 4; i++)
#pragma unroll
        for (int j = 0; j < 4; j++)
#pragma unroll
            for (int v = 0; v < 4; v++) acc[i][j][v] = 0.f;

    gemm_core_h(sbase, Ah, Wh, m0, n0, acc);

    const int wm0 = (wid & 1) * 64, wn0 = (wid >> 1) * 32;
    const int rbase = m0 + wm0 + (lane >> 2);
    const int cbase = n0 + wn0 + (lane & 3) * 2;
#pragma unroll
    for (int mf = 0; mf < 4; mf++) {
#pragma unroll
        for (int nf = 0; nf < 4; nf++) {
#pragma unroll
            for (int half = 0; half < 2; half++) {
                const int r = rbase + mf * 16 + half * 8;
                const int c = cbase + nf * 8;
                const size_t idx = (size_t)r * Hdim + c;
                float2 rv = *(const float2*)(res + idx);
                float2 o;
                o.x = fmaf(acc[mf][nf][half*2+0], WDSC, bias[c] + rv.x);
                o.y = fmaf(acc[mf][nf][half*2+1], WDSC, bias[c+1] + rv.y);
                *(float2*)(out + idx) = o;
            }
        }
    }
}

// ---------------- fp16 flash attention: 64q/128thr CTA, 3-stage ring, reversed order ----------------
#define ALD 72
#define A_TEN 9216
#define A_STG 18432
#define A_QOFF 55296
__global__ void __launch_bounds__(128) attn_mma(
    const __half* __restrict__ Qh, const __half* __restrict__ Kh,
    const __half* __restrict__ Vh, __half* __restrict__ Ch)
{
    extern __shared__ char dsm[];
    const uint32_t sbase = smem_u32(dsm);
    const int tid = threadIdx.x, wid = tid >> 5, lane = tid & 31;
    const int qt = (int)gridDim.x - 1 - (int)blockIdx.x;
    const int h = blockIdx.y, b = blockIdx.z;
    const int m0 = qt * 64, wq0 = wid * 16;
    const int ktmax = qt;
    const size_t base = (size_t)(b * NHn + h) * Slen * HDn;

    {
        const __half* srcH = Qh + base + (size_t)m0 * HDn;
#pragma unroll
        for (int i = 0; i < 4; i++) {
            int u = i * 128 + tid, r = u >> 3, c = u & 7;
            int cs = c ^ ((r & 3) << 1);
            *(uint4*)(dsm + A_QOFF + (r * ALD + cs * 8) * 2) = *(const uint4*)(srcH + r * 64 + c * 8);
        }
    }
    __syncthreads();

    const int rA = (lane & 7) + ((lane >> 3) & 1) * 8;
    const int cA = (lane >> 4) & 1;
    const int rB = (lane & 7) + ((lane >> 4) << 3);
    const int cB = (lane >> 3) & 1;
    const int swzA = (rA & 3) << 1;
    const int swzB = (rB & 3) << 1;

    uint32_t qfh[4][4];
    {
        const int row = wq0 + rA;
        const uint32_t rb = (uint32_t)(row * (ALD * 2));
        const int swz = (row & 3) << 1;
#pragma unroll
        for (int kb = 0; kb < 4; kb++) {
            const uint32_t off = rb + (uint32_t)(((2 * kb + cA) ^ swz) * 16);
            LDSM_X4(qfh[kb][0], qfh[kb][1], qfh[kb][2], qfh[kb][3], sbase + A_QOFF + off);
        }
    }

#define A_LOAD(st, k0) do { \
        const uint32_t sb_ = sbase + (st) * A_STG; \
        const __half* kp_ = Kh + base + (size_t)(k0) * HDn; \
        const __half* vp_ = Vh + base + (size_t)(k0) * HDn; \
        _Pragma("unroll") \
        for (int i_ = 0; i_ < 4; i_++) { \
            int u_ = i_ * 128 + tid, r_ = u_ >> 3, c_ = u_ & 7; \
            int cs_ = c_ ^ ((r_ & 3) << 1); \
            uint32_t so_ = (uint32_t)((r_ * ALD + cs_ * 8) * 2); \
            int go_ = r_ * 64 + c_ * 8; \
            cp16(sb_ + so_,         kp_ + go_); \
            cp16(sb_ + A_TEN + so_, vp_ + go_); \
        } } while (0)

    A_LOAD(0, 0);
    CP_COMMIT();
    if (ktmax >= 1) { A_LOAD(1, 64); CP_COMMIT(); }

    float o[8][4];
#pragma unroll
    for (int i = 0; i < 8; i++)
#pragma unroll
        for (int v = 0; v < 4; v++) o[i][v] = 0.f;
    float mr0 = -1e30f, mr1 = -1e30f, lr0 = 0.f, lr1 = 0.f;

    for (int kt = 0; kt <= ktmax; kt++) {
        if (kt < ktmax) { CP_WAIT(1); } else { CP_WAIT(0); }
        __syncthreads();
        if (kt + 2 <= ktmax) {
            A_LOAD((kt + 2) % 3, (kt + 2) * 64);
            CP_COMMIT();
        }

        const uint32_t sb = sbase + (kt % 3) * A_STG;
        const uint32_t aKh = sb, aVh = sb + A_TEN;

        float s[8][4];
#pragma unroll
        for (int i = 0; i < 8; i++)
#pragma unroll
            for (int v = 0; v < 4; v++) s[i][v] = 0.f;
#pragma unroll
        for (int kb = 0; kb < 4; kb++) {
#pragma unroll
            for (int np = 0; np < 4; np++) {
                const int row = np * 16 + rB;
                const uint32_t off = (uint32_t)(row * (ALD * 2) + (((2 * kb + cB) ^ swzB)) * 16);
                uint32_t kh[4];
                LDSM_X4(kh[0], kh[1], kh[2], kh[3], aKh + off);
                MMAH(s[2*np],   qfh[kb], kh);
                MMAH(s[2*np+1], qfh[kb], kh + 2);
            }
        }

#pragma unroll
        for (int nf = 0; nf < 8; nf++)
#pragma unroll
            for (int v = 0; v < 4; v++) s[nf][v] *= 0.125f;
        if (kt == qt) {
            const int row0 = wq0 + (lane >> 2), row1 = row0 + 8;
            const int colb = (lane & 3) * 2;
#pragma unroll
            for (int nf = 0; nf < 8; nf++) {
                const int c0 = nf * 8 + colb, c1 = c0 + 1;
                if (c0 > row0) s[nf][0] = -1e30f;
                if (c1 > row0) s[nf][1] = -1e30f;
                if (c0 > row1) s[nf][2] = -1e30f;
                if (c1 > row1) s[nf][3] = -1e30f;
            }
        }

        float mx0 = s[0][0], mx1 = s[0][2];
#pragma unroll
        for (int nf = 0; nf < 8; nf++) {
            mx0 = fmaxf(mx0, fmaxf(s[nf][0], s[nf][1]));
            mx1 = fmaxf(mx1, fmaxf(s[nf][2], s[nf][3]));
        }
        mx0 = fmaxf(mx0, __shfl_xor_sync(0xffffffffu, mx0, 1));
        mx0 = fmaxf(mx0, __shfl_xor_sync(0xffffffffu, mx0, 2));
        mx1 = fmaxf(mx1, __shfl_xor_sync(0xffffffffu, mx1, 1));
        mx1 = fmaxf(mx1, __shfl_xor_sync(0xffffffffu, mx1, 2));
        const float nm0 = fmaxf(mr0, mx0), nm1 = fmaxf(mr1, mx1);
        const float cr0 = __expf(mr0 - nm0), cr1 = __expf(mr1 - nm1);
        lr0 *= cr0; lr1 *= cr1;
#pragma unroll
        for (int nf = 0; nf < 8; nf++) {
            o[nf][0] *= cr0; o[nf][1] *= cr0;
            o[nf][2] *= cr1; o[nf][3] *= cr1;
        }
        mr0 = nm0; mr1 = nm1;

        uint32_t ph[8], phb[8];
#pragma unroll
        for (int nf = 0; nf < 8; nf++) {
            float p0 = __expf(s[nf][0] - nm0), p1 = __expf(s[nf][1] - nm0);
            float p2 = __expf(s[nf][2] - nm1), p3 = __expf(s[nf][3] - nm1);
            lr0 += p0 + p1; lr1 += p2 + p3;
            ph[nf]  = pk_h2(p0, p1);
            phb[nf] = pk_h2(p2, p3);
        }

#pragma unroll
        for (int kb = 0; kb < 4; kb++) {
            uint32_t pah[4] = { ph[2*kb], phb[2*kb], ph[2*kb+1], phb[2*kb+1] };
            const int row = kb * 16 + rA;
            const uint32_t rb = (uint32_t)(row * (ALD * 2));
#pragma unroll
            for (int np = 0; np < 4; np++) {
                const uint32_t off = rb + (uint32_t)(((2 * np + cA) ^ swzA) * 16);
                uint32_t vh[4];
                LDSM_X4_T(vh[0], vh[1], vh[2], vh[3], aVh + off);
                MMAH(o[2*np],   pah, vh);
                MMAH(o[2*np+1], pah, vh + 2);
            }
        }
    }
#undef A_LOAD

    lr0 += __shfl_xor_sync(0xffffffffu, lr0, 1);
    lr0 += __shfl_xor_sync(0xffffffffu, lr0, 2);
    lr1 += __shfl_xor_sync(0xffffffffu, lr1, 1);
    lr1 += __shfl_xor_sync(0xffffffffu, lr1, 2);
    const float iv0 = 1.f / lr0, iv1 = 1.f / lr1;

    const int s0 = m0 + wq0 + (lane >> 2), s1 = s0 + 8;
    const size_t rb0 = (size_t)(b * Slen + s0) * Hdim + h * 64;
    const size_t rb1 = (size_t)(b * Slen + s1) * Hdim + h * 64;
#pragma unroll
    for (int nf = 0; nf < 8; nf++) {
        const int col = nf * 8 + (lane & 3) * 2;
        *(uint32_t*)(Ch + rb0 + col) = pk_h2(o[nf][0] * iv0, o[nf][1] * iv0);
        *(uint32_t*)(Ch + rb1 + col) = pk_h2(o[nf][2] * iv1, o[nf][3] * iv1);
    }
}

// ---------------- LayerNorm ----------------
__global__ void ln_kernel(const float* __restrict__ y, const float* __restrict__ g,
                          const float* __restrict__ be, float* __restrict__ out)
{
    __shared__ float red[256];
    const int row = blockIdx.x, tid = threadIdx.x;
    const float4 v = ((const float4*)(y + (size_t)row * Hdim))[tid];
    float sum = v.x + v.y + v.z + v.w;
    red[tid] = sum; __syncthreads();
    for (int s = 128; s > 0; s >>= 1) { if (tid < s) red[tid] += red[tid + s]; __syncthreads(); }
    const float mu = red[0] * (1.f / 1024.f);
    __syncthreads();
    const float d0 = v.x - mu, d1 = v.y - mu, d2 = v.z - mu, d3 = v.w - mu;
    red[tid] = d0 * d0 + d1 * d1 + d2 * d2 + d3 * d3; __syncthreads();
    for (int s = 128; s > 0; s >>= 1) { if (tid < s) red[tid] += red[tid + s]; __syncthreads(); }
    const float inv = rsqrtf(red[0] * (1.f / 1024.f) + EPSf);
    const float4 gg = ((const float4*)g)[tid];
    const float4 bb = ((const float4*)be)[tid];
    float4 o;
    o.x = d0 * inv * gg.x + bb.x;
    o.y = d1 * inv * gg.y + bb.y;
    o.z = d2 * inv * gg.z + bb.z;
    o.w = d3 * inv * gg.w + bb.w;
    ((float4*)(out + (size_t)row * Hdim))[tid] = o;
}

// ---------------- launch ----------------
extern "C" void kernel_launch(void* const* d_in, const int* in_sizes, int n_in,
                              void* d_out, int out_size)
{
    const float* x    = (const float*)d_in[0];
    const float* Wq   = (const float*)d_in[1];
    const float* bq   = (const float*)d_in[2];
    const float* Wk   = (const float*)d_in[3];
    const float* bk   = (const float*)d_in[4];
    const float* Wv   = (const float*)d_in[5];
    const float* bv   = (const float*)d_in[6];
    const float* Wo   = (const float*)d_in[7];
    const float* bo   = (const float*)d_in[8];
    const float* ln_g = (const float*)d_in[9];
    const float* ln_b = (const float*)d_in[10];
    float* out = (float*)d_out;

    float* yp;
    __half *xh, *wh, *qh, *kh, *vh, *ch;
    cudaGetSymbolAddress((void**)&yp, g_y);
    cudaGetSymbolAddress((void**)&xh, g_xh);
    cudaGetSymbolAddress((void**)&wh, g_wh);
    cudaGetSymbolAddress((void**)&qh, g_qh);
    cudaGetSymbolAddress((void**)&kh, g_kh);
    cudaGetSymbolAddress((void**)&vh, g_vh);
    cudaGetSymbolAddress((void**)&ch, g_ch);

    static bool attr_done = false;
    if (!attr_done) {
        cudaFuncSetAttribute(gemm_qkv, cudaFuncAttributeMaxDynamicSharedMemorySize, 3 * GS);
        cudaFuncSetAttribute(gemm_out, cudaFuncAttributeMaxDynamicSharedMemorySize, 3 * GS);
        cudaFuncSetAttribute(attn_mma, cudaFuncAttributeMaxDynamicSharedMemorySize, A_QOFF + A_TEN);
        attr_done = true;
    }

    const int WSZ = Hdim * Hdim;
    prep_kernel<<<8192, 256>>>(x, Wq, Wk, Wv, Wo, xh, wh);

    gemm_qkv<<<dim3(3 * Hdim / 128, Mtot / 128), 256, 3 * GS>>>(
        xh, wh, bq, bk, bv, qh, kh, vh);

    attn_mma<<<dim3(Slen / 64, NHn, Bsz), 128, A_QOFF + A_TEN>>>(qh, kh, vh, ch);

    gemm_out<<<dim3(Hdim / 128, Mtot / 128), 256, 3 * GS>>>(
        ch, wh + 3 * WSZ, bo, x, yp);

    ln_kernel<<<Mtot, 256>>>(yp, ln_g, ln_b, out);
}

// round 17
// speedup vs baseline: 1.7386x; 1.0202x over previous
#include <cuda_runtime.h>
#include <cuda_fp16.h>
#include <stdint.h>
#include <math.h>

#define Bsz   2
#define Slen  2048
#define Hdim  1024
#define NHn   16
#define HDn   64
#define Mtot  (Bsz*Slen)
#define EPSf  1e-12f
#define WSCL  256.f
#define WDSC  (1.f/256.f)

// -------- scratch (no allocations allowed) --------
__device__ float g_y[Mtot*Hdim];
__device__ __half g_xh[Mtot*Hdim];
__device__ __half g_wh[4*Hdim*Hdim];
__device__ __half g_qh[Mtot*Hdim];
__device__ __half g_kh[Mtot*Hdim];
__device__ __half g_vh[Mtot*Hdim];
__device__ __half g_ch[Mtot*Hdim];

// ---------------- helpers ----------------
__device__ __forceinline__ uint32_t smem_u32(const void* p) {
    uint32_t a;
    asm("{ .reg .u64 t; cvta.to.shared.u64 t, %1; cvt.u32.u64 %0, t; }" : "=r"(a) : "l"(p));
    return a;
}
__device__ __forceinline__ void cp16(uint32_t dst, const void* src) {
    asm volatile("cp.async.cg.shared.global [%0], [%1], 16;" :: "r"(dst), "l"(src));
}
#define CP_COMMIT() asm volatile("cp.async.commit_group;")
#define CP_WAIT(n)  asm volatile("cp.async.wait_group %0;" :: "n"(n))
#define LDSM_X4(r0,r1,r2,r3,addr) \
    asm volatile("ldmatrix.sync.aligned.m8n8.x4.shared.b16 {%0,%1,%2,%3}, [%4];" \
        : "=r"(r0),"=r"(r1),"=r"(r2),"=r"(r3) : "r"(addr))
#define LDSM_X4_T(r0,r1,r2,r3,addr) \
    asm volatile("ldmatrix.sync.aligned.m8n8.x4.trans.shared.b16 {%0,%1,%2,%3}, [%4];" \
        : "=r"(r0),"=r"(r1),"=r"(r2),"=r"(r3) : "r"(addr))
#define MMAH(c, a, b) \
    asm volatile("mma.sync.aligned.m16n8k16.row.col.f32.f16.f16.f32 " \
        "{%0,%1,%2,%3}, {%4,%5,%6,%7}, {%8,%9}, {%0,%1,%2,%3};" \
        : "+f"((c)[0]),"+f"((c)[1]),"+f"((c)[2]),"+f"((c)[3]) \
        : "r"((a)[0]),"r"((a)[1]),"r"((a)[2]),"r"((a)[3]), "r"((b)[0]),"r"((b)[1]))

__device__ __forceinline__ uint32_t pk_h2(float a, float b) {
    __half2 h = __floats2half2_rn(a, b);
    return *(uint32_t*)&h;
}

// ---------------- fused prep ----------------
__global__ void prep_kernel(const float* __restrict__ x,
                            const float* __restrict__ Wq, const float* __restrict__ Wk,
                            const float* __restrict__ Wv, const float* __restrict__ Wo,
                            __half* __restrict__ xh, __half* __restrict__ wh)
{
    const int bid = blockIdx.x, tid = threadIdx.x;
    if (bid < 4096) {
        const int i = bid * 256 + tid;
        float4 v = ((const float4*)x)[i];
        __half2 a = __floats2half2_rn(v.x, v.y);
        __half2 b = __floats2half2_rn(v.z, v.w);
        ((uint2*)xh)[i] = make_uint2(*(uint32_t*)&a, *(uint32_t*)&b);
    } else {
        const int wb = bid - 4096;
        const int w = wb >> 10;
        const float* src = (w == 0) ? Wq : (w == 1) ? Wk : (w == 2) ? Wv : Wo;
        const int i = (wb & 1023) * 256 + tid;
        float4 v = ((const float4*)src)[i];
        __half2 a = __floats2half2_rn(v.x * WSCL, v.y * WSCL);
        __half2 b = __floats2half2_rn(v.z * WSCL, v.w * WSCL);
        ((uint2*)(wh + (size_t)w * Hdim * Hdim))[i] = make_uint2(*(uint32_t*)&a, *(uint32_t*)&b);
    }
}

// ---------------- fp16 GEMM core: 3-stage ring, BK=64, c^(r&7) swizzle, W-frag pipeline ----------------
#define GT 16384
#define GS 32768

__device__ __forceinline__ void gemm_core_h(
    uint32_t sbase,
    const __half* __restrict__ Ah, const __half* __restrict__ Wh,
    int m0, int n0, float acc[4][4][4])
{
    const int tid = threadIdx.x, wid = tid >> 5, lane = tid & 31;
    const int wm0 = (wid & 1) * 64, wn0 = (wid >> 1) * 32;
    const int a_row = wm0 + (lane & 15);
    const int b_row = wn0 + (lane & 7) + ((lane >> 4) << 3);
    const int cA = (lane >> 4) & 1;
    const int cB = (lane >> 3) & 1;
    const int lrr = tid >> 3;
    const int lcc = tid & 7;

#define GH_LOAD(st, k0) do { \
        const uint32_t sb_ = sbase + (st) * GS; \
        _Pragma("unroll") \
        for (int i_ = 0; i_ < 4; i_++) { \
            const int r_ = i_ * 32 + lrr; \
            const int cs_ = lcc ^ (r_ & 7); \
            const uint32_t off_ = (uint32_t)(r_ * 128 + cs_ * 16); \
            cp16(sb_ + off_,      Ah + (size_t)(m0 + r_) * Hdim + (k0) + lcc * 8); \
            cp16(sb_ + GT + off_, Wh + (size_t)(n0 + r_) * Hdim + (k0) + lcc * 8); \
        } } while (0)

#define LD_W(dst, base, kf) do { \
        const int rowW0_ = b_row; \
        const int csW0_ = (2 * (kf) + cB) ^ (rowW0_ & 7); \
        LDSM_X4((dst)[0], (dst)[1], (dst)[2], (dst)[3], \
                (base) + (uint32_t)(rowW0_ * 128 + csW0_ * 16)); \
        const int rowW1_ = b_row + 16; \
        const int csW1_ = (2 * (kf) + cB) ^ (rowW1_ & 7); \
        LDSM_X4((dst)[4], (dst)[5], (dst)[6], (dst)[7], \
                (base) + (uint32_t)(rowW1_ * 128 + csW1_ * 16)); \
    } while (0)

    GH_LOAD(0, 0);
    CP_COMMIT();
    GH_LOAD(1, 64);
    CP_COMMIT();

    for (int it = 0; it < 16; it++) {
        if (it < 15) { CP_WAIT(1); } else { CP_WAIT(0); }
        __syncthreads();
        if (it + 2 < 16) {
            GH_LOAD((it + 2) % 3, (it + 2) * 64);
            CP_COMMIT();
        }

        const uint32_t sb = sbase + (it % 3) * GS;
        const uint32_t aA = sb, aW = sb + GT;

        uint32_t wbuf[2][8];
        LD_W(wbuf[0], aW, 0);          // prefetch kf=0 W frags

#pragma unroll
        for (int kf = 0; kf < 4; kf++) {
            uint32_t ah[4][4];
#pragma unroll
            for (int mf = 0; mf < 4; mf++) {
                const int row = a_row + mf * 16;
                const int cs = (2 * kf + cA) ^ (row & 7);
                LDSM_X4(ah[mf][0], ah[mf][1], ah[mf][2], ah[mf][3],
                        aA + (uint32_t)(row * 128 + cs * 16));
            }
            if (kf < 3) LD_W(wbuf[(kf + 1) & 1], aW, kf + 1);

            const uint32_t* w = wbuf[kf & 1];
#pragma unroll
            for (int mf = 0; mf < 4; mf++) {
                MMAH(acc[mf][0], ah[mf], w + 0);
                MMAH(acc[mf][1], ah[mf], w + 2);
                MMAH(acc[mf][2], ah[mf], w + 4);
                MMAH(acc[mf][3], ah[mf], w + 6);
            }
        }
    }
#undef LD_W
#undef GH_LOAD
}

// ---- fused QKV projection ----
__global__ void __launch_bounds__(256, 2) gemm_qkv(
    const __half* __restrict__ Ah, const __half* __restrict__ Wh,
    const float* __restrict__ bq, const float* __restrict__ bk, const float* __restrict__ bv,
    __half* __restrict__ qh, __half* __restrict__ kh, __half* __restrict__ vh)
{
    extern __shared__ char dsm[];
    const uint32_t sbase = smem_u32(dsm);
    const int tid = threadIdx.x, wid = tid >> 5, lane = tid & 31;
    const int n0 = blockIdx.x * 128, m0 = blockIdx.y * 128;

    float acc[4][4][4];
#pragma unroll
    for (int i = 0; i < 4; i++)
#pragma unroll
        for (int j = 0; j < 4; j++)
#pragma unroll
            for (int v = 0; v < 4; v++) acc[i][j][v] = 0.f;

    gemm_core_h(sbase, Ah, Wh, m0, n0, acc);

    const int proj = n0 >> 10;
    const float* bias = (proj == 0) ? bq : (proj == 1) ? bk : bv;
    __half* outH = (proj == 0) ? qh : (proj == 1) ? kh : vh;

    const int wm0 = (wid & 1) * 64, wn0 = (wid >> 1) * 32;
    const int rbase = m0 + wm0 + (lane >> 2);
    const int cbase = n0 + wn0 + (lane & 3) * 2;
#pragma unroll
    for (int mf = 0; mf < 4; mf++) {
#pragma unroll
        for (int nf = 0; nf < 4; nf++) {
#pragma unroll
            for (int half = 0; half < 2; half++) {
                const int r = rbase + mf * 16 + half * 8;
                const int c = cbase + nf * 8;
                const int np = c & 1023;
                float v0 = fmaf(acc[mf][nf][half*2+0], WDSC, bias[np]);
                float v1 = fmaf(acc[mf][nf][half*2+1], WDSC, bias[np+1]);
                const int b = r >> 11, s = r & (Slen - 1);
                const int h = np >> 6, d = np & 63;
                const size_t idx = (((size_t)(b * NHn + h) * Slen) + s) * HDn + d;
                *(uint32_t*)(outH + idx) = pk_h2(v0, v1);
            }
        }
    }
}

// ---- output projection ----
__global__ void __launch_bounds__(256, 2) gemm_out(
    const __half* __restrict__ Ah, const __half* __restrict__ Wh,
    const float* __restrict__ bias, const float* __restrict__ res, float* __restrict__ out)
{
    extern __shared__ char dsm[];
    const uint32_t sbase = smem_u32(dsm);
    const int tid = threadIdx.x, wid = tid >> 5, lane = tid & 31;
    const int n0 = blockIdx.x * 128, m0 = blockIdx.y * 128;

    float acc[4][4][4];
#pragma unroll
    for (int i = 0; i < 4; i++)
#pragma unroll
        for (int j = 0; j < 4; j++)
#pragma unroll
            for (int v = 0; v < 4; v++) acc[i][j][v] = 0.f;

    gemm_core_h(sbase, Ah, Wh, m0, n0, acc);

    const int wm0 = (wid & 1) * 64, wn0 = (wid >> 1) * 32;
    const int rbase = m0 + wm0 + (lane >> 2);
    const int cbase = n0 + wn0 + (lane & 3) * 2;
#pragma unroll
    for (int mf = 0; mf < 4; mf++) {
#pragma unroll
        for (int nf = 0; nf < 4; nf++) {
#pragma unroll
            for (int half = 0; half < 2; half++) {
                const int r = rbase + mf * 16 + half * 8;
                const int c = cbase + nf * 8;
                const size_t idx = (size_t)r * Hdim + c;
                float2 rv = *(const float2*)(res + idx);
                float2 o;
                o.x = fmaf(acc[mf][nf][half*2+0], WDSC, bias[c] + rv.x);
                o.y = fmaf(acc[mf][nf][half*2+1], WDSC, bias[c+1] + rv.y);
                *(float2*)(out + idx) = o;
            }
        }
    }
}

// ---------------- fp16 flash attention: 64q/128thr CTA, 3-stage ring, reversed order ----------------
#define ALD 72
#define A_TEN 9216
#define A_STG 18432
#define A_QOFF 55296
__global__ void __launch_bounds__(128) attn_mma(
    const __half* __restrict__ Qh, const __half* __restrict__ Kh,
    const __half* __restrict__ Vh, __half* __restrict__ Ch)
{
    extern __shared__ char dsm[];
    const uint32_t sbase = smem_u32(dsm);
    const int tid = threadIdx.x, wid = tid >> 5, lane = tid & 31;
    const int qt = (int)gridDim.x - 1 - (int)blockIdx.x;
    const int h = blockIdx.y, b = blockIdx.z;
    const int m0 = qt * 64, wq0 = wid * 16;
    const int ktmax = qt;
    const size_t base = (size_t)(b * NHn + h) * Slen * HDn;

    {
        const __half* srcH = Qh + base + (size_t)m0 * HDn;
#pragma unroll
        for (int i = 0; i < 4; i++) {
            int u = i * 128 + tid, r = u >> 3, c = u & 7;
            int cs = c ^ ((r & 3) << 1);
            *(uint4*)(dsm + A_QOFF + (r * ALD + cs * 8) * 2) = *(const uint4*)(srcH + r * 64 + c * 8);
        }
    }
    __syncthreads();

    const int rA = (lane & 7) + ((lane >> 3) & 1) * 8;
    const int cA = (lane >> 4) & 1;
    const int rB = (lane & 7) + ((lane >> 4) << 3);
    const int cB = (lane >> 3) & 1;
    const int swzA = (rA & 3) << 1;
    const int swzB = (rB & 3) << 1;

    uint32_t qfh[4][4];
    {
        const int row = wq0 + rA;
        const uint32_t rb = (uint32_t)(row * (ALD * 2));
        const int swz = (row & 3) << 1;
#pragma unroll
        for (int kb = 0; kb < 4; kb++) {
            const uint32_t off = rb + (uint32_t)(((2 * kb + cA) ^ swz) * 16);
            LDSM_X4(qfh[kb][0], qfh[kb][1], qfh[kb][2], qfh[kb][3], sbase + A_QOFF + off);
        }
    }

#define A_LOAD(st, k0) do { \
        const uint32_t sb_ = sbase + (st) * A_STG; \
        const __half* kp_ = Kh + base + (size_t)(k0) * HDn; \
        const __half* vp_ = Vh + base + (size_t)(k0) * HDn; \
        _Pragma("unroll") \
        for (int i_ = 0; i_ < 4; i_++) { \
            int u_ = i_ * 128 + tid, r_ = u_ >> 3, c_ = u_ & 7; \
            int cs_ = c_ ^ ((r_ & 3) << 1); \
            uint32_t so_ = (uint32_t)((r_ * ALD + cs_ * 8) * 2); \
            int go_ = r_ * 64 + c_ * 8; \
            cp16(sb_ + so_,         kp_ + go_); \
            cp16(sb_ + A_TEN + so_, vp_ + go_); \
        } } while (0)

    A_LOAD(0, 0);
    CP_COMMIT();
    if (ktmax >= 1) { A_LOAD(1, 64); CP_COMMIT(); }

    float o[8][4];
#pragma unroll
    for (int i = 0; i < 8; i++)
#pragma unroll
        for (int v = 0; v < 4; v++) o[i][v] = 0.f;
    float mr0 = -1e30f, mr1 = -1e30f, lr0 = 0.f, lr1 = 0.f;

    for (int kt = 0; kt <= ktmax; kt++) {
        if (kt < ktmax) { CP_WAIT(1); } else { CP_WAIT(0); }
        __syncthreads();
        if (kt + 2 <= ktmax) {
            A_LOAD((kt + 2) % 3, (kt + 2) * 64);
            CP_COMMIT();
        }

        const uint32_t sb = sbase + (kt % 3) * A_STG;
        const uint32_t aKh = sb, aVh = sb + A_TEN;

        float s[8][4];
#pragma unroll
        for (int i = 0; i < 8; i++)
#pragma unroll
            for (int v = 0; v < 4; v++) s[i][v] = 0.f;
#pragma unroll
        for (int kb = 0; kb < 4; kb++) {
#pragma unroll
            for (int np = 0; np < 4; np++) {
                const int row = np * 16 + rB;
                const uint32_t off = (uint32_t)(row * (ALD * 2) + (((2 * kb + cB) ^ swzB)) * 16);
                uint32_t kh[4];
                LDSM_X4(kh[0], kh[1], kh[2], kh[3], aKh + off);
                MMAH(s[2*np],   qfh[kb], kh);
                MMAH(s[2*np+1], qfh[kb], kh + 2);
            }
        }

#pragma unroll
        for (int nf = 0; nf < 8; nf++)
#pragma unroll
            for (int v = 0; v < 4; v++) s[nf][v] *= 0.125f;
        if (kt == qt) {
            const int row0 = wq0 + (lane >> 2), row1 = row0 + 8;
            const int colb = (lane & 3) * 2;
#pragma unroll
            for (int nf = 0; nf < 8; nf++) {
                const int c0 = nf * 8 + colb, c1 = c0 + 1;
                if (c0 > row0) s[nf][0] = -1e30f;
                if (c1 > row0) s[nf][1] = -1e30f;
                if (c0 > row1) s[nf][2] = -1e30f;
                if (c1 > row1) s[nf][3] = -1e30f;
            }
        }

        float mx0 = s[0][0], mx1 = s[0][2];
#pragma unroll
        for (int nf = 0; nf < 8; nf++) {
            mx0 = fmaxf(mx0, fmaxf(s[nf][0], s[nf][1]));
            mx1 = fmaxf(mx1, fmaxf(s[nf][2], s[nf][3]));
        }
        mx0 = fmaxf(mx0, __shfl_xor_sync(0xffffffffu, mx0, 1));
        mx0 = fmaxf(mx0, __shfl_xor_sync(0xffffffffu, mx0, 2));
        mx1 = fmaxf(mx1, __shfl_xor_sync(0xffffffffu, mx1, 1));
        mx1 = fmaxf(mx1, __shfl_xor_sync(0xffffffffu, mx1, 2));
        const float nm0 = fmaxf(mr0, mx0), nm1 = fmaxf(mr1, mx1);
        const float cr0 = __expf(mr0 - nm0), cr1 = __expf(mr1 - nm1);
        lr0 *= cr0; lr1 *= cr1;
#pragma unroll
        for (int nf = 0; nf < 8; nf++) {
            o[nf][0] *= cr0; o[nf][1] *= cr0;
            o[nf][2] *= cr1; o[nf][3] *= cr1;
        }
        mr0 = nm0; mr1 = nm1;

        uint32_t ph[8], phb[8];
#pragma unroll
        for (int nf = 0; nf < 8; nf++) {
            float p0 = __expf(s[nf][0] - nm0), p1 = __expf(s[nf][1] - nm0);
            float p2 = __expf(s[nf][2] - nm1), p3 = __expf(s[nf][3] - nm1);
            lr0 += p0 + p1; lr1 += p2 + p3;
            ph[nf]  = pk_h2(p0, p1);
            phb[nf] = pk_h2(p2, p3);
        }

#pragma unroll
        for (int kb = 0; kb < 4; kb++) {
            uint32_t pah[4] = { ph[2*kb], phb[2*kb], ph[2*kb+1], phb[2*kb+1] };
            const int row = kb * 16 + rA;
            const uint32_t rb = (uint32_t)(row * (ALD * 2));
#pragma unroll
            for (int np = 0; np < 4; np++) {
                const uint32_t off = rb + (uint32_t)(((2 * np + cA) ^ swzA) * 16);
                uint32_t vh[4];
                LDSM_X4_T(vh[0], vh[1], vh[2], vh[3], aVh + off);
                MMAH(o[2*np],   pah, vh);
                MMAH(o[2*np+1], pah, vh + 2);
            }
        }
    }
#undef A_LOAD

    lr0 += __shfl_xor_sync(0xffffffffu, lr0, 1);
    lr0 += __shfl_xor_sync(0xffffffffu, lr0, 2);
    lr1 += __shfl_xor_sync(0xffffffffu, lr1, 1);
    lr1 += __shfl_xor_sync(0xffffffffu, lr1, 2);
    const float iv0 = 1.f / lr0, iv1 = 1.f / lr1;

    const int s0 = m0 + wq0 + (lane >> 2), s1 = s0 + 8;
    const size_t rb0 = (size_t)(b * Slen + s0) * Hdim + h * 64;
    const size_t rb1 = (size_t)(b * Slen + s1) * Hdim + h * 64;
#pragma unroll
    for (int nf = 0; nf < 8; nf++) {
        const int col = nf * 8 + (lane & 3) * 2;
        *(uint32_t*)(Ch + rb0 + col) = pk_h2(o[nf][0] * iv0, o[nf][1] * iv0);
        *(uint32_t*)(Ch + rb1 + col) = pk_h2(o[nf][2] * iv1, o[nf][3] * iv1);
    }
}

// ---------------- LayerNorm (warp-shuffle reduction) ----------------
__global__ void ln_kernel(const float* __restrict__ y, const float* __restrict__ g,
                          const float* __restrict__ be, float* __restrict__ out)
{
    __shared__ float red[16];
    const int row = blockIdx.x, tid = threadIdx.x;
    const int wid = tid >> 5, lane = tid & 31;
    const float4 v = ((const float4*)(y + (size_t)row * Hdim))[tid];

    float sum = v.x + v.y + v.z + v.w;
    float sq  = v.x * v.x + v.y * v.y + v.z * v.z + v.w * v.w;
#pragma unroll
    for (int s = 16; s > 0; s >>= 1) {
        sum += __shfl_xor_sync(0xffffffffu, sum, s);
        sq  += __shfl_xor_sync(0xffffffffu, sq,  s);
    }
    if (lane == 0) { red[wid] = sum; red[wid + 8] = sq; }
    __syncthreads();
    float ts = red[lane & 7], tq = red[(lane & 7) + 8];
#pragma unroll
    for (int s = 4; s > 0; s >>= 1) {
        ts += __shfl_xor_sync(0xffffffffu, ts, s);
        tq += __shfl_xor_sync(0xffffffffu, tq, s);
    }
    const float mu = ts * (1.f / 1024.f);
    const float var = tq * (1.f / 1024.f) - mu * mu;
    const float inv = rsqrtf(var + EPSf);

    const float4 gg = ((const float4*)g)[tid];
    const float4 bb = ((const float4*)be)[tid];
    float4 o;
    o.x = (v.x - mu) * inv * gg.x + bb.x;
    o.y = (v.y - mu) * inv * gg.y + bb.y;
    o.z = (v.z - mu) * inv * gg.z + bb.z;
    o.w = (v.w - mu) * inv * gg.w + bb.w;
    ((float4*)(out + (size_t)row * Hdim))[tid] = o;
}

// ---------------- launch ----------------
extern "C" void kernel_launch(void* const* d_in, const int* in_sizes, int n_in,
                              void* d_out, int out_size)
{
    const float* x    = (const float*)d_in[0];
    const float* Wq   = (const float*)d_in[1];
    const float* bq   = (const float*)d_in[2];
    const float* Wk   = (const float*)d_in[3];
    const float* bk   = (const float*)d_in[4];
    const float* Wv   = (const float*)d_in[5];
    const float* bv   = (const float*)d_in[6];
    const float* Wo   = (const float*)d_in[7];
    const float* bo   = (const float*)d_in[8];
    const float* ln_g = (const float*)d_in[9];
    const float* ln_b = (const float*)d_in[10];
    float* out = (float*)d_out;

    float* yp;
    __half *xh, *wh, *qh, *kh, *vh, *ch;
    cudaGetSymbolAddress((void**)&yp, g_y);
    cudaGetSymbolAddress((void**)&xh, g_xh);
    cudaGetSymbolAddress((void**)&wh, g_wh);
    cudaGetSymbolAddress((void**)&qh, g_qh);
    cudaGetSymbolAddress((void**)&kh, g_kh);
    cudaGetSymbolAddress((void**)&vh, g_vh);
    cudaGetSymbolAddress((void**)&ch, g_ch);

    static bool attr_done = false;
    if (!attr_done) {
        cudaFuncSetAttribute(gemm_qkv, cudaFuncAttributeMaxDynamicSharedMemorySize, 3 * GS);
        cudaFuncSetAttribute(gemm_out, cudaFuncAttributeMaxDynamicSharedMemorySize, 3 * GS);
        cudaFuncSetAttribute(attn_mma, cudaFuncAttributeMaxDynamicSharedMemorySize, A_QOFF + A_TEN);
        attr_done = true;
    }

    const int WSZ = Hdim * Hdim;
    prep_kernel<<<8192, 256>>>(x, Wq, Wk, Wv, Wo, xh, wh);

    gemm_qkv<<<dim3(3 * Hdim / 128, Mtot / 128), 256, 3 * GS>>>(
        xh, wh, bq, bk, bv, qh, kh, vh);

    attn_mma<<<dim3(Slen / 64, NHn, Bsz), 128, A_QOFF + A_TEN>>>(qh, kh, vh, ch);

    gemm_out<<<dim3(Hdim / 128, Mtot / 128), 256, 3 * GS>>>(
        ch, wh + 3 * WSZ, bo, x, yp);

    ln_kernel<<<Mtot, 256>>>(yp, ln_g, ln_b, out);
}